// round 11
// baseline (speedup 1.0000x reference)
#include <cuda_runtime.h>

#define T_STEPS 2048
#define B_SZ    64
#define H_SZ    256
#define BH      (B_SZ * H_SZ)

typedef unsigned long long u64;

__device__ float g_seqA[(size_t)T_STEPS * BH];
__device__ float g_seqB[(size_t)T_STEPS * BH];
struct PaddedCtr { unsigned int v; unsigned int pad[31]; };
__device__ PaddedCtr g_bar[3][4];

__global__ void reset_kernel() {
    int i = threadIdx.x;
    if (i < 12) g_bar[i / 4][i % 4].v = 0u;
}

__device__ __forceinline__ void ffma2(u64 &d, u64 a, u64 b) {
    asm("fma.rn.f32x2 %0, %1, %2, %0;" : "+l"(d) : "l"(a), "l"(b));
}
__device__ __forceinline__ u64 pack2(float lo, float hi) {
    u64 r; asm("mov.b64 %0, {%1, %2};" : "=l"(r) : "f"(lo), "f"(hi)); return r;
}
__device__ __forceinline__ float2 unpack2(u64 v) {
    float2 r; asm("mov.b64 {%0, %1}, %2;" : "=f"(r.x), "=f"(r.y) : "l"(v)); return r;
}
__device__ __forceinline__ float fsigmoid(float x) {
    float e; asm("ex2.approx.f32 %0, %1;" : "=f"(e) : "f"(-1.4426950408889634f * x));
    float r; asm("rcp.approx.f32 %0, %1;" : "=f"(r) : "f"(1.0f + e));
    return r;
}
__device__ __forceinline__ float ftanh(float x) {
    float y; asm("tanh.approx.f32 %0, %1;" : "=f"(y) : "f"(x)); return y;
}

// Fused scan: 64 CTAs = 16 ug x 4 bg. CTA: 16 units x 16 batches.
// Computes gx = Wih@x_t on the fly (Wih in SMEM) + recurrent Whh@h (regs).
// Layer l>0 polls layer l-1's counters for x availability.
__global__ __launch_bounds__(256, 1) void gru_scan(
    const float* __restrict__ xbase,   // [2048,64,256] this layer's input seq
    const float* __restrict__ h0l,
    const float* __restrict__ Wih,     // [768,256]
    const float* __restrict__ Whh,     // [768,256]
    const float* __restrict__ bih,
    const float* __restrict__ bhh,
    float* __restrict__ seqout,
    float* __restrict__ hn_out,
    int layer, int has_prev)
{
    extern __shared__ float sm[];
    float* ws = sm;                    // Wih slice: 48 rows x 256
    float* hs = sm + 48 * 256;         // h_{t-1}: 16 x 256
    float* xs = sm + 64 * 256;         // x_t: 16 x 256

    const int tid = threadIdx.x, w = tid >> 5, l = tid & 31;
    const int ks = l & 15, bh = l >> 4;
    const int bg = blockIdx.x & 3, ug = blockIdx.x >> 2;
    const int u0 = ug * 16 + w * 2;
    const int bgrp0 = bg * 16, b0l = bh * 8;

    int rows[6];
    rows[0] = u0;       rows[1] = u0 + 1;
    rows[2] = 256 + u0; rows[3] = 257 + u0;
    rows[4] = 512 + u0; rows[5] = 513 + u0;

    u64 wk[6][8];
#pragma unroll
    for (int r = 0; r < 6; r++)
#pragma unroll
        for (int kk = 0; kk < 4; kk++) {
            float4 v = *(const float4*)(Whh + (size_t)rows[r] * 256 + kk * 64 + ks * 4);
            wk[r][kk * 2 + 0] = pack2(v.x, v.y);
            wk[r][kk * 2 + 1] = pack2(v.z, v.w);
        }
    float bh6[6], bi6[6];
#pragma unroll
    for (int r = 0; r < 6; r++) { bh6[r] = bhh[rows[r]]; bi6[r] = bih[rows[r]]; }

    // Wih rows for this CTA's 16 units into SMEM: lr = g*16+lu
    for (int idx = tid; idx < 48 * 64; idx += 256) {
        int lr = idx >> 6, c4 = idx & 63;
        int g = lr >> 4, lu = lr & 15;
        *(float4*)&ws[lr * 256 + c4 * 4] =
            *(const float4*)(Wih + (size_t)(g * 256 + ug * 16 + lu) * 256 + c4 * 4);
    }
    // per-warp ws row offsets (local units 2w, 2w+1)
    int wsrow[6];
#pragma unroll
    for (int g = 0; g < 3; g++) {
        wsrow[2 * g]     = (g * 16 + 2 * w)     * 256;
        wsrow[2 * g + 1] = (g * 16 + 2 * w + 1) * 256;
    }
    __syncthreads();

    unsigned int* ctr  = &g_bar[layer][bg].v;
    unsigned int* pctr = &g_bar[layer ? layer - 1 : 0][bg].v;
    const int  j       = ks;
    const bool is_comb = (ks < 8);
    const bool hi8     = ((ks & 8) != 0);
    const int  bl      = b0l + j;
    const int  gb      = bgrp0 + bl;

    for (int t = 0; t < T_STEPS; t++) {
        if (t > 0) {
            const unsigned int tg = (unsigned int)t * 16u; unsigned int v;
            do { asm volatile("ld.acquire.gpu.global.u32 %0, [%1];"
                              : "=r"(v) : "l"(ctr) : "memory"); } while (v < tg);
        }
        if (has_prev) {
            const unsigned int tg = (unsigned int)(t + 1) * 16u; unsigned int v;
            do { asm volatile("ld.acquire.gpu.global.u32 %0, [%1];"
                              : "=r"(v) : "l"(pctr) : "memory"); } while (v < tg);
        }

        // stage h_{t-1} and x_t (16 rows each, contiguous)
        {
            const float* hsrc = (t == 0) ? h0l : (seqout + (size_t)(t - 1) * BH);
            const float4* h4 = (const float4*)(hsrc + (size_t)bgrp0 * 256);
            const float4* x4 = (const float4*)(xbase + (size_t)t * BH + (size_t)bgrp0 * 256);
            float4* hd = (float4*)hs; float4* xd = (float4*)xs;
#pragma unroll
            for (int i = 0; i < 4; i++) {
                hd[tid + 256 * i] = __ldcg(h4 + tid + 256 * i);
                xd[tid + 256 * i] = __ldcg(x4 + tid + 256 * i);
            }
        }
        __syncthreads();

        float hold0 = 0.0f, hold1 = 0.0f;
        if (is_comb) { hold0 = hs[bl * 256 + u0 - ug * 16 + ug * 16]; }
        if (is_comb) { hold0 = hs[bl * 256 + u0]; hold1 = hs[bl * 256 + u0 + 1]; }
        // NOTE: hs rows are LOCAL units? No: hs holds full 256-unit h rows; index u0 ok.

#pragma unroll
        for (int bp = 0; bp < 4; bp++) {
            const int lA = b0l + 2 * bp, lB = lA + 1;
            // q: 0,1=r(u0,u1) 2,3=z 4,5=n-hidden 6,7=n-input ; [A,B]
            u64 acc[8][2];
#pragma unroll
            for (int q = 0; q < 8; q++) { acc[q][0] = 0ULL; acc[q][1] = 0ULL; }
#pragma unroll
            for (int kk = 0; kk < 4; kk++) {
                const int ko = kk * 64 + ks * 4;
                ulonglong2 hA = *(const ulonglong2*)&hs[lA * 256 + ko];
                ulonglong2 hB = *(const ulonglong2*)&hs[lB * 256 + ko];
                ulonglong2 xA = *(const ulonglong2*)&xs[lA * 256 + ko];
                ulonglong2 xB = *(const ulonglong2*)&xs[lB * 256 + ko];
#pragma unroll
                for (int r = 0; r < 6; r++) {
                    const int qh = (r < 4) ? r : (r + 0);      // r,z -> 0..3 ; nh -> 4,5
                    ffma2(acc[qh][0], wk[r][kk * 2 + 0], hA.x);
                    ffma2(acc[qh][0], wk[r][kk * 2 + 1], hA.y);
                    ffma2(acc[qh][1], wk[r][kk * 2 + 0], hB.x);
                    ffma2(acc[qh][1], wk[r][kk * 2 + 1], hB.y);
                }
#pragma unroll
                for (int r = 0; r < 6; r++) {
                    const int qx = (r < 4) ? r : (r + 2);      // r,z merge ; nx -> 6,7
                    ulonglong2 wv = *(const ulonglong2*)&ws[wsrow[r] + ko];
                    ffma2(acc[qx][0], wv.x, xA.x);
                    ffma2(acc[qx][0], wv.y, xA.y);
                    ffma2(acc[qx][1], wv.x, xB.x);
                    ffma2(acc[qx][1], wv.y, xB.y);
                }
            }
            // split-reduce: lanes ks<8 end with A totals, ks>=8 with B totals
            float keep[8];
#pragma unroll
            for (int q = 0; q < 8; q++) {
                float2 a = unpack2(acc[q][0]); float sA = a.x + a.y;
                float2 b = unpack2(acc[q][1]); float sB = b.x + b.y;
                float send = hi8 ? sA : sB;
                float recv = __shfl_xor_sync(0xFFFFFFFFu, send, 8);
                keep[q] = (hi8 ? sB : sA) + recv;
            }
#pragma unroll
            for (int off = 1; off < 8; off <<= 1)
#pragma unroll
                for (int q = 0; q < 8; q++)
                    keep[q] += __shfl_xor_sync(0xFFFFFFFFu, keep[q], off);
            float fetched[8];
#pragma unroll
            for (int q = 0; q < 8; q++)
                fetched[q] = __shfl_sync(0xFFFFFFFFu, keep[q], (l & 15) | 8, 16);

            if (is_comb && (j >> 1) == bp) {
                const float* s = (j & 1) ? fetched : keep;
                float r0 = fsigmoid(s[0] + bi6[0] + bh6[0]);
                float z0 = fsigmoid(s[2] + bi6[2] + bh6[2]);
                float n0 = ftanh(s[6] + bi6[4] + r0 * (s[4] + bh6[4]));
                float out0 = (1.0f - z0) * n0 + z0 * hold0;
                float r1 = fsigmoid(s[1] + bi6[1] + bh6[1]);
                float z1 = fsigmoid(s[3] + bi6[3] + bh6[3]);
                float n1 = ftanh(s[7] + bi6[5] + r1 * (s[5] + bh6[5]));
                float out1 = (1.0f - z1) * n1 + z1 * hold1;
                u64 o = pack2(out0, out1);
                *(u64*)&seqout[((size_t)t * B_SZ + gb) * H_SZ + u0] = o;
                if (t == T_STEPS - 1) *(u64*)&hn_out[gb * 256 + u0] = o;
            }
        }

        __syncthreads();
        if (tid == 0)
            asm volatile("red.release.gpu.global.add.u32 [%0], 1;"
                         :: "l"(ctr) : "memory");
    }
}

extern "C" void kernel_launch(void* const* d_in, const int* in_sizes, int n_in,
                              void* d_out, int out_size)
{
    const float* x   = (const float*)d_in[0];
    const float* h0  = (const float*)d_in[1];
    const float* Wih = (const float*)d_in[2];
    const float* Whh = (const float*)d_in[3];
    const float* bih = (const float*)d_in[4];
    const float* bhh = (const float*)d_in[5];

    float* out     = (float*)d_out;
    float* hn_base = out + (size_t)T_STEPS * BH;

    void *pa = nullptr, *pb = nullptr;
    cudaGetSymbolAddress(&pa, g_seqA);
    cudaGetSymbolAddress(&pb, g_seqB);
    float* seqA = (float*)pa;
    float* seqB = (float*)pb;

    static cudaStream_t s2 = nullptr;
    static cudaEvent_t evFork;
    const int SMEM = 80 * 256 * 4;   // 81920 B
    if (!s2) {
        cudaStreamCreateWithFlags(&s2, cudaStreamNonBlocking);
        cudaEventCreateWithFlags(&evFork, cudaEventDisableTiming);
        cudaFuncSetAttribute(gru_scan, cudaFuncAttributeMaxDynamicSharedMemorySize, SMEM);
    }

    const size_t WS = (size_t)768 * 256;
    const size_t HS = (size_t)BH;

    reset_kernel<<<1, 32>>>();
    cudaEventRecord(evFork, 0);
    cudaStreamWaitEvent(s2, evFork, 0);

    // L0 on default stream, L1 on s2 (fine-grained pipelined via counters),
    // L2 on default stream (starts after L0's grid retires; L1 done by then).
    gru_scan<<<64, 256, SMEM, 0>>>(x, h0, Wih, Whh, bih, bhh,
                                   seqA, hn_base, 0, 0);
    gru_scan<<<64, 256, SMEM, s2>>>(seqA, h0 + HS, Wih + WS, Whh + WS,
                                    bih + 768, bhh + 768,
                                    seqB, hn_base + HS, 1, 1);
    gru_scan<<<64, 256, SMEM, 0>>>(seqB, h0 + 2 * HS, Wih + 2 * WS, Whh + 2 * WS,
                                   bih + 2 * 768, bhh + 2 * 768,
                                   out, hn_base + 2 * HS, 2, 1);

    // default stream must also not outpace L1's completion for correctness of
    // graph-end; L2 polls L1's counters device-side, so ordering is safe.
    cudaEventRecord(evFork, s2);
    cudaStreamWaitEvent(0, evFork, 0);
}

// round 13
// speedup vs baseline: 1.1756x; 1.1756x over previous
#include <cuda_runtime.h>

#define T_STEPS 2048
#define B_SZ    64
#define H_SZ    256
#define G3      768
#define BH      (B_SZ * H_SZ)
#define M_TOT   (T_STEPS * B_SZ)
#define NCHUNK  8
#define CHUNK_T (T_STEPS / NCHUNK)     // 256
#define CHUNK_M (CHUNK_T * B_SZ)       // 16384

typedef unsigned long long u64;

__device__ float g_gx[(size_t)M_TOT * G3];      // gx, reused by all 3 layers
__device__ float g_seqA[(size_t)T_STEPS * BH];  // L0 out / L1 in
__device__ float g_seqB[(size_t)T_STEPS * BH];  // L1 out / L2 in
struct PaddedCtr { unsigned int v; unsigned int pad[31]; };
__device__ PaddedCtr g_bar[3][2];               // [layer][bg], 16 CTAs each

__global__ void reset_kernel() {
    int i = threadIdx.x;
    if (i < 6) g_bar[i >> 1][i & 1].v = 0u;
}

__device__ __forceinline__ void ffma2(u64 &d, u64 a, u64 b) {
    asm("fma.rn.f32x2 %0, %1, %2, %0;" : "+l"(d) : "l"(a), "l"(b));
}
__device__ __forceinline__ u64 pack2(float lo, float hi) {
    u64 r; asm("mov.b64 %0, {%1, %2};" : "=l"(r) : "f"(lo), "f"(hi)); return r;
}
__device__ __forceinline__ float2 unpack2(u64 v) {
    float2 r; asm("mov.b64 {%0, %1}, %2;" : "=f"(r.x), "=f"(r.y) : "l"(v)); return r;
}
__device__ __forceinline__ float fsigmoid(float x) {
    float e; asm("ex2.approx.f32 %0, %1;" : "=f"(e) : "f"(-1.4426950408889634f * x));
    float r; asm("rcp.approx.f32 %0, %1;" : "=f"(r) : "f"(1.0f + e));
    return r;
}
__device__ __forceinline__ float ftanh(float x) {
    float y; asm("tanh.approx.f32 %0, %1;" : "=f"(y) : "f"(x)); return y;
}

// ---------------- Phase A: gx GEMM (FFMA2, chunked; numerics verified R3) ----
__global__ __launch_bounds__(256) void gemm_gx(
    const float* __restrict__ A, const float* __restrict__ W,
    const float* __restrict__ bias, int m_base)
{
    __shared__ __align__(16) float As[32 * 132];
    __shared__ __align__(16) float Bs[32 * 64];
    const int tid = threadIdx.x, tx = tid & 15, ty = tid >> 4;
    const int m0 = m_base + blockIdx.x * 128, n0 = blockIdx.y * 64;

    u64 acc[4][4];
#pragma unroll
    for (int i = 0; i < 4; i++)
#pragma unroll
        for (int j = 0; j < 4; j++) acc[i][j] = 0ULL;

    for (int k0 = 0; k0 < 256; k0 += 32) {
#pragma unroll
        for (int i = 0; i < 4; i++) {
            int f = tid + 256 * i, r = f >> 3, c4 = f & 7;
            float4 v = *(const float4*)(A + (size_t)(m0 + r) * 256 + k0 + c4 * 4);
            As[(c4 * 4 + 0) * 132 + r] = v.x;
            As[(c4 * 4 + 1) * 132 + r] = v.y;
            As[(c4 * 4 + 2) * 132 + r] = v.z;
            As[(c4 * 4 + 3) * 132 + r] = v.w;
        }
#pragma unroll
        for (int i = 0; i < 2; i++) {
            int f = tid + 256 * i, r = f >> 3, c4 = f & 7;
            float4 v = *(const float4*)(W + (size_t)(n0 + r) * 256 + k0 + c4 * 4);
            Bs[(c4 * 4 + 0) * 64 + r] = v.x;
            Bs[(c4 * 4 + 1) * 64 + r] = v.y;
            Bs[(c4 * 4 + 2) * 64 + r] = v.z;
            Bs[(c4 * 4 + 3) * 64 + r] = v.w;
        }
        __syncthreads();
#pragma unroll
        for (int k = 0; k < 32; k++) {
            const u64* ap = (const u64*)&As[k * 132 + ty * 8];
            u64 a0 = ap[0], a1 = ap[1], a2 = ap[2], a3 = ap[3];
            float4 bv = *(const float4*)&Bs[k * 64 + tx * 4];
            u64 b0 = pack2(bv.x, bv.x), b1 = pack2(bv.y, bv.y);
            u64 b2 = pack2(bv.z, bv.z), b3 = pack2(bv.w, bv.w);
            ffma2(acc[0][0], a0, b0); ffma2(acc[0][1], a0, b1);
            ffma2(acc[0][2], a0, b2); ffma2(acc[0][3], a0, b3);
            ffma2(acc[1][0], a1, b0); ffma2(acc[1][1], a1, b1);
            ffma2(acc[1][2], a1, b2); ffma2(acc[1][3], a1, b3);
            ffma2(acc[2][0], a2, b0); ffma2(acc[2][1], a2, b1);
            ffma2(acc[2][2], a2, b2); ffma2(acc[2][3], a2, b3);
            ffma2(acc[3][0], a3, b0); ffma2(acc[3][1], a3, b1);
            ffma2(acc[3][2], a3, b2); ffma2(acc[3][3], a3, b3);
        }
        __syncthreads();
    }
    float4 bv = *(const float4*)(bias + n0 + tx * 4);
#pragma unroll
    for (int i = 0; i < 4; i++) {
        float2 c0 = unpack2(acc[i][0]), c1 = unpack2(acc[i][1]);
        float2 c2 = unpack2(acc[i][2]), c3 = unpack2(acc[i][3]);
        float4 e, o;
        e.x = c0.x + bv.x; e.y = c1.x + bv.y; e.z = c2.x + bv.z; e.w = c3.x + bv.w;
        o.x = c0.y + bv.x; o.y = c1.y + bv.y; o.z = c2.y + bv.z; o.w = c3.y + bv.w;
        *(float4*)(g_gx + (size_t)(m0 + ty * 8 + 2 * i)     * G3 + n0 + tx * 4) = e;
        *(float4*)(g_gx + (size_t)(m0 + ty * 8 + 2 * i + 1) * G3 + n0 + tx * 4) = o;
    }
}

// ---------------- Phase B: scan. 32 CTAs = 16 ug x 2 bg ----------------------
// CTA: 16 units x 32 batches. Warp w: units u0 = ug*16 + 2w. Lane owns one
// batch: ob = (l>>4)*16 + 2*(ks&7) + (ks>=8). Pass p reduces batches
// {2p, 2p+1} of each half via split-reduce; owning lanes combine (no
// divergent gather, no cross-batch shuffle fetch).
__global__ __launch_bounds__(256, 1) void gru_scan(
    const float* __restrict__ h0l, const float* __restrict__ Whh,
    const float* __restrict__ bhh, float* __restrict__ seqout,
    float* __restrict__ hn_out, int t0, int t1, int layer)
{
    __shared__ __align__(16) float hs[32 * 256];   // 32 KB staged h

    const int tid = threadIdx.x, w = tid >> 5, l = tid & 31;
    const int ks = l & 15, bh = l >> 4;
    const int bg = blockIdx.x & 1, ug = blockIdx.x >> 1;
    const int u0 = ug * 16 + w * 2;
    const int bgrp0 = bg * 32, b0l = bh * 16;
    const bool hi8 = (ks & 8) != 0;
    const int ob = b0l + 2 * (ks & 7) + (hi8 ? 1 : 0);
    const int gb = bgrp0 + ob;

    int rows[6];
    rows[0] = u0;       rows[1] = u0 + 1;
    rows[2] = 256 + u0; rows[3] = 257 + u0;
    rows[4] = 512 + u0; rows[5] = 513 + u0;

    u64 wk[6][8];
#pragma unroll
    for (int r = 0; r < 6; r++)
#pragma unroll
        for (int kk = 0; kk < 4; kk++) {
            float4 v = *(const float4*)(Whh + (size_t)rows[r] * 256 + kk * 64 + ks * 4);
            wk[r][kk * 2 + 0] = pack2(v.x, v.y);
            wk[r][kk * 2 + 1] = pack2(v.z, v.w);
        }
    float bh6[6];
#pragma unroll
    for (int r = 0; r < 6; r++) bh6[r] = bhh[rows[r]];

    unsigned int* ctr = &g_bar[layer][bg].v;

    u64 gxv0, gxv1, gxv2;
    {
        const float* gp = g_gx + ((size_t)t0 * B_SZ + gb) * G3;
        gxv0 = *(const u64*)(gp + u0);
        gxv1 = *(const u64*)(gp + 256 + u0);
        gxv2 = *(const u64*)(gp + 512 + u0);
    }

    for (int t = t0; t < t1; t++) {
        if (t > 0) {
            const unsigned int tg = (unsigned int)t * 16u; unsigned int v;
            do { asm volatile("ld.acquire.gpu.global.u32 %0, [%1];"
                              : "=r"(v) : "l"(ctr) : "memory"); } while (v < tg);
        }
        {
            const float* hsrc = (t == 0) ? h0l : (seqout + (size_t)(t - 1) * BH);
            const float4* s4 = (const float4*)(hsrc + (size_t)bgrp0 * 256);
            float4* d4 = (float4*)hs;
#pragma unroll
            for (int i = 0; i < 8; i++)
                d4[tid + 256 * i] = __ldcg(s4 + tid + 256 * i);
        }
        __syncthreads();

        const float hold0 = hs[ob * 256 + u0];
        const float hold1 = hs[ob * 256 + u0 + 1];

#pragma unroll
        for (int p = 0; p < 8; p++) {
            const int lA = b0l + 2 * p, lB = lA + 1;
            u64 acc[6][2];
#pragma unroll
            for (int r = 0; r < 6; r++) { acc[r][0] = 0ULL; acc[r][1] = 0ULL; }
#pragma unroll
            for (int kk = 0; kk < 4; kk++) {
                const int ko = kk * 64 + ks * 4;
                ulonglong2 hA = *(const ulonglong2*)&hs[lA * 256 + ko];
                ulonglong2 hB = *(const ulonglong2*)&hs[lB * 256 + ko];
#pragma unroll
                for (int r = 0; r < 6; r++) {
                    ffma2(acc[r][0], wk[r][kk * 2 + 0], hA.x);
                    ffma2(acc[r][0], wk[r][kk * 2 + 1], hA.y);
                    ffma2(acc[r][1], wk[r][kk * 2 + 0], hB.x);
                    ffma2(acc[r][1], wk[r][kk * 2 + 1], hB.y);
                }
            }
            float keep[6];
#pragma unroll
            for (int r = 0; r < 6; r++) {
                float2 a = unpack2(acc[r][0]); float sA = a.x + a.y;
                float2 b = unpack2(acc[r][1]); float sB = b.x + b.y;
                float send = hi8 ? sA : sB;
                float recv = __shfl_xor_sync(0xFFFFFFFFu, send, 8);
                keep[r] = (hi8 ? sB : sA) + recv;
            }
#pragma unroll
            for (int off = 1; off < 8; off <<= 1)
#pragma unroll
                for (int r = 0; r < 6; r++)
                    keep[r] += __shfl_xor_sync(0xFFFFFFFFu, keep[r], off);

            if ((ks & 7) == p) {
                float2 gxr = unpack2(gxv0), gxz = unpack2(gxv1), gxn = unpack2(gxv2);
                float r0 = fsigmoid(gxr.x + keep[0] + bh6[0]);
                float z0 = fsigmoid(gxz.x + keep[2] + bh6[2]);
                float n0 = ftanh(gxn.x + r0 * (keep[4] + bh6[4]));
                float out0 = (1.0f - z0) * n0 + z0 * hold0;
                float r1 = fsigmoid(gxr.y + keep[1] + bh6[1]);
                float z1 = fsigmoid(gxz.y + keep[3] + bh6[3]);
                float n1 = ftanh(gxn.y + r1 * (keep[5] + bh6[5]));
                float out1 = (1.0f - z1) * n1 + z1 * hold1;
                u64 o = pack2(out0, out1);
                *(u64*)&seqout[((size_t)t * B_SZ + gb) * H_SZ + u0] = o;
                if (t == T_STEPS - 1) *(u64*)&hn_out[gb * 256 + u0] = o;
            }
        }

        if (t + 1 < t1) {
            const float* gp = g_gx + ((size_t)(t + 1) * B_SZ + gb) * G3;
            gxv0 = *(const u64*)(gp + u0);
            gxv1 = *(const u64*)(gp + 256 + u0);
            gxv2 = *(const u64*)(gp + 512 + u0);
        }

        __syncthreads();
        if (tid == 0)
            asm volatile("red.release.gpu.global.add.u32 [%0], 1;"
                         :: "l"(ctr) : "memory");
    }
}

// ---------------- launch: gemm on capture stream, 3 scan streams -------------
extern "C" void kernel_launch(void* const* d_in, const int* in_sizes, int n_in,
                              void* d_out, int out_size)
{
    const float* x   = (const float*)d_in[0];
    const float* h0  = (const float*)d_in[1];
    const float* Wih = (const float*)d_in[2];
    const float* Whh = (const float*)d_in[3];
    const float* bih = (const float*)d_in[4];
    const float* bhh = (const float*)d_in[5];

    float* out     = (float*)d_out;
    float* hn_base = out + (size_t)T_STEPS * BH;

    void *pa = nullptr, *pb = nullptr;
    cudaGetSymbolAddress(&pa, g_seqA);
    cudaGetSymbolAddress(&pb, g_seqB);
    float* seqA = (float*)pa;
    float* seqB = (float*)pb;

    static cudaStream_t ssc[3] = {nullptr, nullptr, nullptr};
    static cudaEvent_t evFork, evG[3][NCHUNK], evS[3][NCHUNK];
    if (!ssc[0]) {
        for (int i = 0; i < 3; i++)
            cudaStreamCreateWithFlags(&ssc[i], cudaStreamNonBlocking);
        cudaEventCreateWithFlags(&evFork, cudaEventDisableTiming);
        for (int lyr = 0; lyr < 3; lyr++)
            for (int c = 0; c < NCHUNK; c++) {
                cudaEventCreateWithFlags(&evG[lyr][c], cudaEventDisableTiming);
                cudaEventCreateWithFlags(&evS[lyr][c], cudaEventDisableTiming);
            }
    }

    const size_t WS = (size_t)G3 * 256;
    const size_t HS = (size_t)BH;
    const dim3 ggrid(CHUNK_M / 128, G3 / 64);   // (128, 12)

    const float* gemmA[3]   = { x, seqA, seqB };
    float*       scanOut[3] = { seqA, seqB, out };

    reset_kernel<<<1, 32>>>();                       // launch 0
    cudaEventRecord(evFork, 0);
    for (int i = 0; i < 3; i++) cudaStreamWaitEvent(ssc[i], evFork, 0);

    // gemm L0 chunks 0..3 (launches 1-4), then scan L0 c0 as launch 5 (ncu -s 5)
    for (int c = 0; c < 4; c++) {
        gemm_gx<<<ggrid, 256>>>(x, Wih, bih, c * CHUNK_M);
        cudaEventRecord(evG[0][c], 0);
    }
    cudaStreamWaitEvent(ssc[0], evG[0][0], 0);
    gru_scan<<<32, 256, 0, ssc[0]>>>(h0, Whh, bhh, scanOut[0], hn_base,
                                     0, CHUNK_T, 0);
    cudaEventRecord(evS[0][0], ssc[0]);

    for (int c = 4; c < NCHUNK; c++) {
        gemm_gx<<<ggrid, 256>>>(x, Wih, bih, c * CHUNK_M);
        cudaEventRecord(evG[0][c], 0);
    }

    for (int c = 0; c < NCHUNK; c++) {
        // scan L0 chunk c (c=0 already issued)
        if (c > 0) {
            cudaStreamWaitEvent(ssc[0], evG[0][c], 0);
            gru_scan<<<32, 256, 0, ssc[0]>>>(h0, Whh, bhh, scanOut[0], hn_base,
                                             c * CHUNK_T, (c + 1) * CHUNK_T, 0);
            cudaEventRecord(evS[0][c], ssc[0]);
        }
        // gemm L1 chunk c, then scan L1 chunk c
        cudaStreamWaitEvent(0, evS[0][c], 0);
        gemm_gx<<<ggrid, 256>>>(gemmA[1], Wih + WS, bih + G3, c * CHUNK_M);
        cudaEventRecord(evG[1][c], 0);
        cudaStreamWaitEvent(ssc[1], evG[1][c], 0);
        gru_scan<<<32, 256, 0, ssc[1]>>>(h0 + HS, Whh + WS, bhh + G3,
                                         scanOut[1], hn_base + HS,
                                         c * CHUNK_T, (c + 1) * CHUNK_T, 1);
        cudaEventRecord(evS[1][c], ssc[1]);
        // gemm L2 chunk c, then scan L2 chunk c
        cudaStreamWaitEvent(0, evS[1][c], 0);
        gemm_gx<<<ggrid, 256>>>(gemmA[2], Wih + 2 * WS, bih + 2 * G3, c * CHUNK_M);
        cudaEventRecord(evG[2][c], 0);
        cudaStreamWaitEvent(ssc[2], evG[2][c], 0);
        gru_scan<<<32, 256, 0, ssc[2]>>>(h0 + 2 * HS, Whh + 2 * WS, bhh + 2 * G3,
                                         scanOut[2], hn_base + 2 * HS,
                                         c * CHUNK_T, (c + 1) * CHUNK_T, 2);
        cudaEventRecord(evS[2][c], ssc[2]);
    }

    // join all scan streams back into the capture stream
    cudaStreamWaitEvent(0, evS[0][NCHUNK - 1], 0);
    cudaStreamWaitEvent(0, evS[1][NCHUNK - 1], 0);
    cudaStreamWaitEvent(0, evS[2][NCHUNK - 1], 0);
}